// round 14
// baseline (speedup 1.0000x reference)
#include <cuda_runtime.h>
#include <cuda_fp16.h>
#include <cstdint>

#define NPTS   50000
#define MPTS   50001
#define DIM    512
#define HID    512
#define TSTEPS 16
#define NBMAX  320
#define NEGINF (__int_as_float(0xff800000))

#define PADM   50048           // 391 * 128
#define ROWT   391
#define NCH    8               // K = 512, 64-wide chunks
#define STGH   (128 * 72 * 2)  // halfs per stage (A + B)
#define FEAT_SMEM (2 * STGH * 2)

// ---------------- device scratch ----------------
__device__ __half g_af16[(size_t)MPTS * DIM];
__device__ __half g_hf16[(size_t)MPTS * DIM];
__device__ __half g_a16[(size_t)PADM * DIM];
__device__ __half g_bt[2][512][512];
__device__ float g_hbuf[2][HID];
__device__ float g_cbuf[2][HID];
__device__ float g_x[DIM];
__device__ float g_qh[HID];
__device__ float g_ba[HID];
__device__ unsigned char g_sel[MPTS];
__device__ int   g_done;
__device__ int   g_ticket;
__device__ volatile int g_xready;
__device__ volatile unsigned g_gen;
__device__ unsigned g_cnt2[8 * 16];   // padded counters (64B apart)
__device__ unsigned g_root;
__device__ float g_hpart[NBMAX][514];
__device__ float g_apart[NBMAX][3];
__device__ int   g_aidx[NBMAX];

// ---------------- helpers ----------------
__device__ __forceinline__ float tanhe(float x) {
    float e = __expf(2.f * x);
    return 1.f - __fdividef(2.f, e + 1.f);
}
__device__ __forceinline__ float tanha(float x) {
    float y; asm("tanh.approx.f32 %0, %1;" : "=f"(y) : "f"(x)); return y;
}
__device__ __forceinline__ float sigm(float x) {
    return __fdividef(1.f, 1.f + __expf(-x));
}
__device__ __forceinline__ uint32_t s2u(const void* p) {
    uint32_t a;
    asm("{ .reg .u64 t; cvta.to.shared.u64 t, %1; cvt.u32.u64 %0, t; }" : "=r"(a) : "l"(p));
    return a;
}
__device__ __forceinline__ void cp16(uint32_t dst, const void* src) {
    asm volatile("cp.async.cg.shared.global [%0], [%1], 16;" :: "r"(dst), "l"(src));
}
__device__ __forceinline__ void ldm4(uint32_t& r0, uint32_t& r1, uint32_t& r2, uint32_t& r3,
                                     uint32_t addr) {
    asm volatile("ldmatrix.sync.aligned.m8n8.x4.shared.b16 {%0,%1,%2,%3}, [%4];"
                 : "=r"(r0), "=r"(r1), "=r"(r2), "=r"(r3) : "r"(addr));
}
__device__ __forceinline__ void mma16816(float* c, uint32_t a0, uint32_t a1, uint32_t a2,
                                         uint32_t a3, uint32_t b0, uint32_t b1) {
    asm volatile(
        "mma.sync.aligned.m16n8k16.row.col.f32.f16.f16.f32 "
        "{%0,%1,%2,%3},{%4,%5,%6,%7},{%8,%9},{%0,%1,%2,%3};"
        : "+f"(c[0]), "+f"(c[1]), "+f"(c[2]), "+f"(c[3])
        : "r"(a0), "r"(a1), "r"(a2), "r"(a3), "r"(b0), "r"(b1));
}
__device__ __forceinline__ unsigned pkh2(float a, float b) {
    __half2 h = __floats2half2_rn(a, b);
    return *(unsigned*)&h;
}

// two-level grid barrier (round-12, measured best)
__device__ __forceinline__ void gridbar(int nb) {
    __threadfence();
    __syncthreads();
    if (threadIdx.x == 0) {
        unsigned gen = g_gen;
        int grp = blockIdx.x & 7;
        unsigned quota = (unsigned)((nb - grp + 7) >> 3);
        unsigned v = atomicAdd(&g_cnt2[grp * 16], 1);
        if (v == quota - 1) {
            g_cnt2[grp * 16] = 0;
            unsigned r = atomicAdd(&g_root, 1);
            if (r == 7) {
                g_root = 0;
                __threadfence();
                g_gen = gen + 1;
            } else {
                while (g_gen == gen) __nanosleep(32);
            }
        } else {
            while (g_gen == gen) __nanosleep(32);
        }
    }
    __syncthreads();
}

// ---------------- K0: merged setup (state init + conv A + conv B) ----------------
__global__ void k_setup(const float* __restrict__ mem, const float* __restrict__ stop,
                        const float* __restrict__ ih, const float* __restrict__ ic,
                        const float* __restrict__ ii,
                        const float* __restrict__ attn_wm, const float* __restrict__ hop_wm) {
    int gtid = blockIdx.x * blockDim.x + threadIdx.x;
    // state init
    if (gtid < MPTS) g_sel[gtid] = 0;
    if (gtid < HID) { g_hbuf[0][gtid] = ih[gtid]; g_cbuf[0][gtid] = ic[gtid];
                      g_x[gtid] = ii[gtid]; g_qh[gtid] = 0.f; }
    if (gtid < 128) g_cnt2[gtid] = 0;
    if (gtid == 0) { g_done = 0; g_ticket = 0; g_gen = 0; g_root = 0; g_xready = 0; }
    // conv B: wm[k][n] -> g_bt[mat][n][k]
    if (gtid < 2 * 512 * 512) {
        int w = gtid >> 18;
        int r = gtid & 262143;
        int n = r >> 9;
        int k = r & 511;
        const float* src = w ? hop_wm : attn_wm;
        g_bt[w][n][k] = __float2half_rn(src[(size_t)k * 512 + n]);
    }
    // conv A (grid-stride)
    const int total4 = PADM * DIM / 4;
    for (int i = gtid; i < total4; i += gridDim.x * blockDim.x) {
        int row = i >> 7;
        int c4 = (i & 127) * 4;
        float4 v;
        if (row < NPTS)       v = *(const float4*)&mem[(size_t)row * DIM + c4];
        else if (row == NPTS) v = *(const float4*)&stop[c4];
        else                  v = make_float4(0.f, 0.f, 0.f, 0.f);
        uint2 ph;
        ph.x = pkh2(v.x, v.y); ph.y = pkh2(v.z, v.w);
        ((uint2*)g_a16)[i] = ph;
    }
}

// ---------------- GEMM: fp16 mma.sync, CTA 128x128, K=512, chunk 64 ----------------
__global__ void __launch_bounds__(256, 2) k_feat_mma() {
    extern __shared__ __align__(16) __half dsm[];
    int tid = threadIdx.x, wid = tid >> 5, lane = tid & 31;
    int rowBase = blockIdx.y * 128;
    int colBase = (blockIdx.x >> 1) * 128;
    int mat = blockIdx.x & 1;
    const __half* bsrc = &g_bt[mat][colBase][0];
    __half* outp = mat ? g_hf16 : g_af16;
    const __half* asrc = g_a16 + (size_t)rowBase * DIM;
    int wm = wid >> 1, wn = wid & 1;

    float acc[2][8][4];
#pragma unroll
    for (int mt = 0; mt < 2; mt++)
#pragma unroll
        for (int j = 0; j < 8; j++)
#pragma unroll
            for (int e = 0; e < 4; e++) acc[mt][j][e] = 0.f;

    uint32_t u0 = s2u(dsm);

    auto load = [&](int c, int buf) {
        const __half* A = asrc + c * 64;
        const __half* B = bsrc + c * 64;
        uint32_t dA = u0 + buf * (STGH * 2);
        uint32_t dB = dA + 128 * 72 * 2;
#pragma unroll
        for (int i = 0; i < 4; i++) {
            int idx = i * 256 + tid;
            int r = idx >> 3, ch = idx & 7;
            cp16(dA + r * 144 + ch * 16, (const char*)(A + (size_t)r * 512) + ch * 16);
            cp16(dB + r * 144 + ch * 16, (const char*)(B + (size_t)r * 512) + ch * 16);
        }
        asm volatile("cp.async.commit_group;" ::: "memory");
    };

    load(0, 0);
    for (int c = 0; c < NCH; c++) {
        int buf = c & 1;
        if (c + 1 < NCH) load(c + 1, buf ^ 1);
        if (c + 1 < NCH)
            asm volatile("cp.async.wait_group 1;" ::: "memory");
        else
            asm volatile("cp.async.wait_group 0;" ::: "memory");
        __syncthreads();

        uint32_t bA = u0 + buf * (STGH * 2);
        uint32_t bB = bA + 128 * 72 * 2;
#pragma unroll
        for (int ks = 0; ks < 4; ks++) {
            uint32_t a[2][4];
#pragma unroll
            for (int mt = 0; mt < 2; mt++) {
                int row = wm * 32 + mt * 16 + (lane & 15);
                int col = ks * 16 + (lane >> 4) * 8;
                ldm4(a[mt][0], a[mt][1], a[mt][2], a[mt][3], bA + (row * 72 + col) * 2);
            }
            uint32_t b[4][4];
#pragma unroll
            for (int p = 0; p < 4; p++) {
                int q = lane >> 3, rr = lane & 7;
                int n = wn * 64 + p * 16 + (q >> 1) * 8 + rr;
                int col = ks * 16 + (q & 1) * 8;
                ldm4(b[p][0], b[p][1], b[p][2], b[p][3], bB + (n * 72 + col) * 2);
            }
#pragma unroll
            for (int mt = 0; mt < 2; mt++)
#pragma unroll
                for (int j = 0; j < 8; j++)
                    mma16816(acc[mt][j], a[mt][0], a[mt][1], a[mt][2], a[mt][3],
                             b[j >> 1][(j & 1) * 2], b[j >> 1][(j & 1) * 2 + 1]);
        }
        __syncthreads();
    }

    int g = lane >> 2, tq = lane & 3;
#pragma unroll
    for (int mt = 0; mt < 2; mt++) {
        int r0 = rowBase + wm * 32 + mt * 16 + g;
#pragma unroll
        for (int j = 0; j < 8; j++) {
            int cc = colBase + wn * 64 + j * 8 + tq * 2;
            if (r0 < MPTS)
                *(__half2*)&outp[(size_t)r0 * DIM + cc] =
                    __floats2half2_rn(acc[mt][j][0], acc[mt][j][1]);
            if (r0 + 8 < MPTS)
                *(__half2*)&outp[(size_t)(r0 + 8) * DIM + cc] =
                    __floats2half2_rn(acc[mt][j][2], acc[mt][j][3]);
        }
    }
}

// ================= persistent step megakernel =================
__global__ void __launch_bounds__(256, 2) k_step(
    const float* __restrict__ w_ih, const float* __restrict__ w_hh,
    const float* __restrict__ b_ih, const float* __restrict__ b_hh,
    const float* __restrict__ hop_wq, const float* __restrict__ hop_v,
    const float* __restrict__ attn_wq, const float* __restrict__ attn_v,
    const float* __restrict__ gumbel, const float* __restrict__ attn_mem,
    const float* __restrict__ stop, float* __restrict__ out, int nb)
{
    __shared__ float sg2[8][4];
    __shared__ float shh[4];
    __shared__ float smx[8], ssw[8], sacc[8][512];
    __shared__ float red[256];
    __shared__ float qn[8];
    __shared__ float sb[8]; __shared__ int si[8];
    __shared__ float sm[8]; __shared__ float ss[8];
    __shared__ float fb[256]; __shared__ int fi[256];
    __shared__ float fm[256]; __shared__ float fs[256];
    __shared__ int s_out, s_nd, islast;

    int bid = blockIdx.x;
    int tid = threadIdx.x, wid = tid >> 5, lane = tid & 31;
    const int tot = nb * 8;
    int gw = bid * 8 + wid;
    // balanced contiguous row range for pass phases
    int rstart = (int)(((long long)gw * MPTS) / tot);
    int rend   = (int)(((long long)(gw + 1) * MPTS) / tot);

    for (int t = 0; t < TSTEPS; t++) {
        // ---- phase A (flag-gated): gates + h,c + qh GEMV (blocks 0..127) ----
        if (bid < 128) {
            if (tid == 0) { while (g_xready < t) __nanosleep(32); }
            __syncthreads();
            __threadfence();
            int kb = bid * 4;
            const float* hold = g_hbuf[t & 1];
            float* hnew = g_hbuf[(t + 1) & 1];
            const float* cold = g_cbuf[t & 1];
            float* cnew = g_cbuf[(t + 1) & 1];
            int j = kb + (wid & 3);
            int k0 = (wid >> 2) * 256;
            const float* wi0 = w_ih + (size_t)j * DIM;
            const float* wi1 = w_ih + (size_t)(HID + j) * DIM;
            const float* wi2 = w_ih + (size_t)(2 * HID + j) * DIM;
            const float* wi3 = w_ih + (size_t)(3 * HID + j) * DIM;
            const float* wh0 = w_hh + (size_t)j * HID;
            const float* wh1 = w_hh + (size_t)(HID + j) * HID;
            const float* wh2 = w_hh + (size_t)(2 * HID + j) * HID;
            const float* wh3 = w_hh + (size_t)(3 * HID + j) * HID;
            float s0 = 0.f, s1 = 0.f, s2 = 0.f, s3 = 0.f;
#pragma unroll 4
            for (int k = k0 + lane; k < k0 + 256; k += 32) {
                float xv = g_x[k], hv = hold[k];
                s0 += wi0[k] * xv + wh0[k] * hv;
                s1 += wi1[k] * xv + wh1[k] * hv;
                s2 += wi2[k] * xv + wh2[k] * hv;
                s3 += wi3[k] * xv + wh3[k] * hv;
            }
#pragma unroll
            for (int o = 16; o; o >>= 1) {
                s0 += __shfl_xor_sync(0xffffffffu, s0, o);
                s1 += __shfl_xor_sync(0xffffffffu, s1, o);
                s2 += __shfl_xor_sync(0xffffffffu, s2, o);
                s3 += __shfl_xor_sync(0xffffffffu, s3, o);
            }
            if (!lane) { sg2[wid][0] = s0; sg2[wid][1] = s1; sg2[wid][2] = s2; sg2[wid][3] = s3; }
            __syncthreads();
            if (tid < 4) {
                int jj = kb + tid;
                float g0 = sg2[tid][0] + sg2[tid + 4][0] + b_ih[jj] + b_hh[jj];
                float g1 = sg2[tid][1] + sg2[tid + 4][1] + b_ih[HID + jj] + b_hh[HID + jj];
                float g2 = sg2[tid][2] + sg2[tid + 4][2] + b_ih[2 * HID + jj] + b_hh[2 * HID + jj];
                float g3 = sg2[tid][3] + sg2[tid + 4][3] + b_ih[3 * HID + jj] + b_hh[3 * HID + jj];
                float gi = sigm(g0);
                float gf = sigm(g1);
                float gg = tanhe(g2);
                float go = sigm(g3);
                float c = gf * cold[jj] + gi * gg;
                float h = go * tanhe(c);
                cnew[jj] = c;
                hnew[jj] = h;
                shh[tid] = h;
            }
            __syncthreads();
            float a0 = 0.f, a1 = 0.f;
#pragma unroll
            for (int kk = 0; kk < 4; kk++) {
                float hv = shh[kk];
                const float* wr = hop_wq + (size_t)(kb + kk) * HID;
                a0 += hv * wr[tid];
                a1 += hv * wr[tid + 256];
            }
            atomicAdd(&g_qh[tid], a0);
            atomicAdd(&g_qh[tid + 256], a1);
        }
        gridbar(nb);

        // ---- phase B: hop pass (balanced contiguous rows, 4/iter) ----
        {
            if (bid == 0) { g_ba[tid] = 0.f; g_ba[tid + 256] = 0.f; }
            float q0[16], v0[16];
            {
                float4 a = *(const float4*)&g_qh[lane * 8];
                float4 b = *(const float4*)&g_qh[lane * 8 + 4];
                float4 c = *(const float4*)&g_qh[256 + lane * 8];
                float4 d = *(const float4*)&g_qh[256 + lane * 8 + 4];
                q0[0]=a.x;q0[1]=a.y;q0[2]=a.z;q0[3]=a.w; q0[4]=b.x;q0[5]=b.y;q0[6]=b.z;q0[7]=b.w;
                q0[8]=c.x;q0[9]=c.y;q0[10]=c.z;q0[11]=c.w; q0[12]=d.x;q0[13]=d.y;q0[14]=d.z;q0[15]=d.w;
                a = *(const float4*)&hop_v[lane * 8];
                b = *(const float4*)&hop_v[lane * 8 + 4];
                c = *(const float4*)&hop_v[256 + lane * 8];
                d = *(const float4*)&hop_v[256 + lane * 8 + 4];
                v0[0]=a.x;v0[1]=a.y;v0[2]=a.z;v0[3]=a.w; v0[4]=b.x;v0[5]=b.y;v0[6]=b.z;v0[7]=b.w;
                v0[8]=c.x;v0[9]=c.y;v0[10]=c.z;v0[11]=c.w; v0[12]=d.x;v0[13]=d.y;v0[14]=d.z;v0[15]=d.w;
            }
            float mx = NEGINF, sw = 0.f, acc[16];
#pragma unroll
            for (int i = 0; i < 16; i++) acc[i] = 0.f;

            for (int m0 = rstart; m0 < rend; m0 += 4) {
                uint4 p[4][2];
                int nrow = rend - m0;
                if (nrow > 4) nrow = 4;
#pragma unroll
                for (int r = 0; r < 4; r++) {
                    if (r < nrow) {
                        const uint4* rp = (const uint4*)(g_hf16 + (size_t)(m0 + r) * DIM);
                        p[r][0] = rp[lane];
                        p[r][1] = rp[32 + lane];
                    }
                }
                float sp[4];
#pragma unroll
                for (int r = 0; r < 4; r++) {
                    sp[r] = 0.f;
                    if (r < nrow) {
#pragma unroll
                        for (int k = 0; k < 4; k++) {
                            float2 f0 = __half22float2(((const __half2*)&p[r][0])[k]);
                            float2 f1 = __half22float2(((const __half2*)&p[r][1])[k]);
                            sp[r] += tanha(f0.x + q0[2*k])     * v0[2*k];
                            sp[r] += tanha(f0.y + q0[2*k+1])   * v0[2*k+1];
                            sp[r] += tanha(f1.x + q0[8+2*k])   * v0[8+2*k];
                            sp[r] += tanha(f1.y + q0[8+2*k+1]) * v0[8+2*k+1];
                        }
                    }
                }
#pragma unroll
                for (int o = 16; o; o >>= 1) {
                    sp[0] += __shfl_xor_sync(0xffffffffu, sp[0], o);
                    sp[1] += __shfl_xor_sync(0xffffffffu, sp[1], o);
                    sp[2] += __shfl_xor_sync(0xffffffffu, sp[2], o);
                    sp[3] += __shfl_xor_sync(0xffffffffu, sp[3], o);
                }
#pragma unroll
                for (int r = 0; r < 4; r++) {
                    if (r >= nrow) break;
                    if (sp[r] > mx) {
                        float f = __expf(mx - sp[r]);
                        sw *= f;
#pragma unroll
                        for (int i = 0; i < 16; i++) acc[i] *= f;
                        mx = sp[r];
                    }
                    float wgt = __expf(sp[r] - mx);
                    sw += wgt;
#pragma unroll
                    for (int k = 0; k < 4; k++) {
                        float2 f0 = __half22float2(((const __half2*)&p[r][0])[k]);
                        float2 f1 = __half22float2(((const __half2*)&p[r][1])[k]);
                        acc[2*k]     += wgt * f0.x;
                        acc[2*k+1]   += wgt * f0.y;
                        acc[8+2*k]   += wgt * f1.x;
                        acc[8+2*k+1] += wgt * f1.y;
                    }
                }
            }
#pragma unroll
            for (int s = 0; s < 8; s++) {
                sacc[wid][lane * 8 + s] = acc[s];
                sacc[wid][256 + lane * 8 + s] = acc[8 + s];
            }
            if (!lane) { smx[wid] = mx; ssw[wid] = sw; }
            __syncthreads();

            float M = smx[0];
#pragma unroll
            for (int w = 1; w < 8; w++) M = fmaxf(M, smx[w]);
            for (int c = tid; c < 512; c += 256) {
                float a = 0.f;
#pragma unroll
                for (int w = 0; w < 8; w++) a += sacc[w][c] * __expf(smx[w] - M);
                g_hpart[bid][2 + c] = a;
            }
            if (tid == 0) {
                float W = 0.f;
#pragma unroll
                for (int w = 0; w < 8; w++) W += ssw[w] * __expf(smx[w] - M);
                g_hpart[bid][0] = M;
                g_hpart[bid][1] = W;
            }
            __syncthreads();
        }
        gridbar(nb);

        // ---- phase C: reduce hop partials + bias GEMV (blocks 0..63) ----
        if (bid < 64) {
            int kb = bid * 8;
            float m = NEGINF;
            for (int b = tid; b < nb; b += 256) m = fmaxf(m, g_hpart[b][0]);
            red[tid] = m; __syncthreads();
            for (int o = 128; o; o >>= 1) { if (tid < o) red[tid] = fmaxf(red[tid], red[tid + o]); __syncthreads(); }
            float M = red[0]; __syncthreads();

            float wsum = 0.f;
            for (int b = tid; b < nb; b += 256) wsum += __expf(g_hpart[b][0] - M) * g_hpart[b][1];
            red[tid] = wsum; __syncthreads();
            for (int o = 128; o; o >>= 1) { if (tid < o) red[tid] += red[tid + o]; __syncthreads(); }
            float W = red[0]; __syncthreads();

            {
                int g = tid >> 5, l = tid & 31;
                int k = kb + g;
                float a = 0.f;
                for (int b = l; b < nb; b += 32)
                    a += __expf(g_hpart[b][0] - M) * g_hpart[b][2 + k];
#pragma unroll
                for (int o = 16; o; o >>= 1) a += __shfl_xor_sync(0xffffffffu, a, o);
                if (l == 0) qn[g] = __fdividef(a, W);
            }
            __syncthreads();

            float a0 = 0.f, a1 = 0.f;
#pragma unroll
            for (int kk = 0; kk < 8; kk++) {
                float q = qn[kk];
                const float* wr = attn_wq + (size_t)(kb + kk) * HID;
                a0 += q * wr[tid];
                a1 += q * wr[tid + 256];
            }
            atomicAdd(&g_ba[tid], a0);
            atomicAdd(&g_ba[tid + 256], a1);
        }
        gridbar(nb);

        // ---- phase D: attn pass (balanced contiguous rows) + ticket-fused final + flag ----
        {
            const float* gum = gumbel + (size_t)t * MPTS;
            float b0[16], v0[16];
            {
                float4 a = *(const float4*)&g_ba[lane * 8];
                float4 b = *(const float4*)&g_ba[lane * 8 + 4];
                float4 c = *(const float4*)&g_ba[256 + lane * 8];
                float4 d = *(const float4*)&g_ba[256 + lane * 8 + 4];
                b0[0]=a.x;b0[1]=a.y;b0[2]=a.z;b0[3]=a.w; b0[4]=b.x;b0[5]=b.y;b0[6]=b.z;b0[7]=b.w;
                b0[8]=c.x;b0[9]=c.y;b0[10]=c.z;b0[11]=c.w; b0[12]=d.x;b0[13]=d.y;b0[14]=d.z;b0[15]=d.w;
                a = *(const float4*)&attn_v[lane * 8];
                b = *(const float4*)&attn_v[lane * 8 + 4];
                c = *(const float4*)&attn_v[256 + lane * 8];
                d = *(const float4*)&attn_v[256 + lane * 8 + 4];
                v0[0]=a.x;v0[1]=a.y;v0[2]=a.z;v0[3]=a.w; v0[4]=b.x;v0[5]=b.y;v0[6]=b.z;v0[7]=b.w;
                v0[8]=c.x;v0[9]=c.y;v0[10]=c.z;v0[11]=c.w; v0[12]=d.x;v0[13]=d.y;v0[14]=d.z;v0[15]=d.w;
            }
            float mxs = NEGINF, ssum = 0.f, best = NEGINF;
            int bidx = 0x7fffffff;

            for (int m0 = rstart; m0 < rend; m0 += 4) {
                uint4 p[4][2];
                int nrow = rend - m0;
                if (nrow > 4) nrow = 4;
#pragma unroll
                for (int r = 0; r < 4; r++) {
                    if (r < nrow) {
                        const uint4* rp = (const uint4*)(g_af16 + (size_t)(m0 + r) * DIM);
                        p[r][0] = rp[lane];
                        p[r][1] = rp[32 + lane];
                    }
                }
#pragma unroll
                for (int r = 0; r < 4; r++) {
                    if (r >= nrow) break;
                    int m = m0 + r;
                    float sp = 0.f;
#pragma unroll
                    for (int k = 0; k < 4; k++) {
                        float2 f0 = __half22float2(((const __half2*)&p[r][0])[k]);
                        float2 f1 = __half22float2(((const __half2*)&p[r][1])[k]);
                        sp += tanha(f0.x + b0[2*k])     * v0[2*k];
                        sp += tanha(f0.y + b0[2*k+1])   * v0[2*k+1];
                        sp += tanha(f1.x + b0[8+2*k])   * v0[8+2*k];
                        sp += tanha(f1.y + b0[8+2*k+1]) * v0[8+2*k+1];
                    }
#pragma unroll
                    for (int o = 16; o; o >>= 1) sp += __shfl_xor_sync(0xffffffffu, sp, o);
                    float sc = g_sel[m] ? -1e18f : sp;
                    if (sc > mxs) { ssum *= __expf(mxs - sc); mxs = sc; }
                    ssum += __expf(sc - mxs);
                    float tv = sc + gum[m];
                    if (tv > best || (tv == best && m < bidx)) { best = tv; bidx = m; }
                }
            }
            if (!lane) { sb[wid] = best; si[wid] = bidx; sm[wid] = mxs; ss[wid] = ssum; }
            __syncthreads();
            if (tid == 0) {
                float B = sb[0]; int I = si[0];
                float M2 = sm[0], S = ss[0];
#pragma unroll
                for (int w = 1; w < 8; w++) {
                    if (sb[w] > B || (sb[w] == B && si[w] < I)) { B = sb[w]; I = si[w]; }
                    float m2 = sm[w], s2 = ss[w];
                    if (m2 > M2) { S = S * __expf(M2 - m2) + s2; M2 = m2; }
                    else S += s2 * __expf(m2 - M2);
                }
                g_apart[bid][0] = B; g_apart[bid][1] = M2;
                g_apart[bid][2] = S; g_aidx[bid] = I;
            }

            __threadfence();
            __syncthreads();
            if (tid == 0) {
                int v = atomicAdd(&g_ticket, 1);
                islast = ((v % nb) == nb - 1);
            }
            __syncthreads();
            if (islast) {
                g_qh[tid] = 0.f; g_qh[tid + 256] = 0.f;
                float B = NEGINF; int I = 0x7fffffff; float M = NEGINF; float S = 0.f;
                for (int b = tid; b < nb; b += 256) {
                    float bb = g_apart[b][0]; int ii = g_aidx[b];
                    if (bb > B || (bb == B && ii < I)) { B = bb; I = ii; }
                    float m2 = g_apart[b][1], s2 = g_apart[b][2];
                    if (m2 > M) { S = S * __expf(M - m2) + s2; M = m2; }
                    else S += s2 * __expf(m2 - M);
                }
                fb[tid] = B; fi[tid] = I; fm[tid] = M; fs[tid] = S;
                __syncthreads();
                for (int o = 128; o; o >>= 1) {
                    if (tid < o) {
                        if (fb[tid + o] > fb[tid] || (fb[tid + o] == fb[tid] && fi[tid + o] < fi[tid])) {
                            fb[tid] = fb[tid + o]; fi[tid] = fi[tid + o];
                        }
                        float m1 = fm[tid], s1 = fs[tid];
                        float m2 = fm[tid + o], s2 = fs[tid + o];
                        float Mn = fmaxf(m1, m2);
                        float Sn = 0.f;
                        if (s1 > 0.f) Sn += s1 * __expf(m1 - Mn);
                        if (s2 > 0.f) Sn += s2 * __expf(m2 - Mn);
                        fm[tid] = Mn; fs[tid] = Sn;
                    }
                    __syncthreads();
                }
                if (tid == 0) {
                    int done = g_done;
                    int o_ = fi[0];
                    float sc = fb[0] - gum[o_];
                    float lse = fm[0] + logf(fs[0]);
                    float logp = sc - lse;
                    out[t]          = done ? (float)NPTS : (float)o_;
                    out[TSTEPS + t] = done ? 0.f : logp;
                    if (!done) g_sel[o_] = 1;
                    int nd = done || (o_ == NPTS);
                    g_done = nd;
                    s_out = o_; s_nd = nd;
                }
                __syncthreads();
                if (!s_nd) {
                    int o_ = s_out;
                    const float* src = (o_ == NPTS) ? stop : attn_mem + (size_t)o_ * DIM;
                    g_x[tid] = src[tid];
                    g_x[tid + 256] = src[tid + 256];
                }
                __threadfence();
                __syncthreads();
                if (tid == 0) g_xready = t + 1;
            }
        }
        // phase A of t+1 is flag-gated; no trailing gridbar
    }
}

// ---------------- launch ----------------
extern "C" void kernel_launch(void* const* d_in, const int* in_sizes, int n_in,
                              void* d_out, int out_size) {
    const float* attn_mem = (const float*)d_in[0];
    const float* stop     = (const float*)d_in[1];
    const float* init_h   = (const float*)d_in[2];
    const float* init_c   = (const float*)d_in[3];
    const float* init_i   = (const float*)d_in[4];
    const float* attn_wm  = (const float*)d_in[5];
    const float* attn_wq  = (const float*)d_in[6];
    const float* attn_v   = (const float*)d_in[7];
    const float* hop_wm   = (const float*)d_in[8];
    const float* hop_wq   = (const float*)d_in[9];
    const float* hop_v    = (const float*)d_in[10];
    const float* w_ih     = (const float*)d_in[11];
    const float* w_hh     = (const float*)d_in[12];
    const float* b_ih     = (const float*)d_in[13];
    const float* b_hh     = (const float*)d_in[14];
    const float* gumbel   = (const float*)d_in[15];
    float* out = (float*)d_out;

    static int nb = 0;
    if (nb == 0) {
        int sms = 0;
        cudaDeviceGetAttribute(&sms, cudaDevAttrMultiProcessorCount, 0);
        nb = 2 * sms;
        if (nb > NBMAX) nb = NBMAX;
        if (nb < 128) nb = 128;
        cudaFuncSetAttribute(k_feat_mma, cudaFuncAttributeMaxDynamicSharedMemorySize, FEAT_SMEM);
    }

    k_setup<<<8192, 256>>>(attn_mem, stop, init_h, init_c, init_i, attn_wm, hop_wm);

    dim3 gg(8, ROWT);
    k_feat_mma<<<gg, 256, FEAT_SMEM>>>();

    k_step<<<nb, 256>>>(w_ih, w_hh, b_ih, b_hh, hop_wq, hop_v,
                        attn_wq, attn_v, gumbel, attn_mem, stop, out, nb);
}

// round 15
// speedup vs baseline: 1.0850x; 1.0850x over previous
#include <cuda_runtime.h>
#include <cuda_fp16.h>
#include <cstdint>

#define NPTS   50000
#define MPTS   50001
#define DIM    512
#define HID    512
#define TSTEPS 16
#define NBMAX  320
#define NEGINF (__int_as_float(0xff800000))

#define PADM   50048           // 391 * 128
#define ROWT   391
#define NCH    8               // K = 512, 64-wide chunks
#define STGH   (128 * 72 * 2)  // halfs per stage (A + B)
#define FEAT_SMEM (2 * STGH * 2)

// ---------------- device scratch ----------------
__device__ __half g_af16[(size_t)MPTS * DIM];
__device__ __half g_hf16[(size_t)MPTS * DIM];
__device__ __half g_a16[(size_t)PADM * DIM];
__device__ __half g_bt[2][512][512];
__device__ float g_hbuf[2][HID];
__device__ float g_cbuf[2][HID];
__device__ float g_x[DIM];
__device__ float g_qh[HID];
__device__ float g_ba[HID];
__device__ unsigned char g_sel[MPTS];
__device__ int   g_done;
__device__ int   g_ticket;
__device__ volatile int g_xready;
__device__ volatile unsigned g_gen;
__device__ unsigned g_cnt2[8 * 16];   // padded counters (64B apart)
__device__ unsigned g_root;
__device__ float g_hpart[NBMAX][514];
__device__ float g_apart[NBMAX][3];
__device__ int   g_aidx[NBMAX];

// ---------------- helpers ----------------
__device__ __forceinline__ float tanhe(float x) {
    float e = __expf(2.f * x);
    return 1.f - __fdividef(2.f, e + 1.f);
}
__device__ __forceinline__ float tanha(float x) {
    float y; asm("tanh.approx.f32 %0, %1;" : "=f"(y) : "f"(x)); return y;
}
__device__ __forceinline__ float sigm(float x) {
    return __fdividef(1.f, 1.f + __expf(-x));
}
__device__ __forceinline__ uint32_t s2u(const void* p) {
    uint32_t a;
    asm("{ .reg .u64 t; cvta.to.shared.u64 t, %1; cvt.u32.u64 %0, t; }" : "=r"(a) : "l"(p));
    return a;
}
__device__ __forceinline__ void cp16(uint32_t dst, const void* src) {
    asm volatile("cp.async.cg.shared.global [%0], [%1], 16;" :: "r"(dst), "l"(src));
}
__device__ __forceinline__ void ldm4(uint32_t& r0, uint32_t& r1, uint32_t& r2, uint32_t& r3,
                                     uint32_t addr) {
    asm volatile("ldmatrix.sync.aligned.m8n8.x4.shared.b16 {%0,%1,%2,%3}, [%4];"
                 : "=r"(r0), "=r"(r1), "=r"(r2), "=r"(r3) : "r"(addr));
}
__device__ __forceinline__ void mma16816(float* c, uint32_t a0, uint32_t a1, uint32_t a2,
                                         uint32_t a3, uint32_t b0, uint32_t b1) {
    asm volatile(
        "mma.sync.aligned.m16n8k16.row.col.f32.f16.f16.f32 "
        "{%0,%1,%2,%3},{%4,%5,%6,%7},{%8,%9},{%0,%1,%2,%3};"
        : "+f"(c[0]), "+f"(c[1]), "+f"(c[2]), "+f"(c[3])
        : "r"(a0), "r"(a1), "r"(a2), "r"(a3), "r"(b0), "r"(b1));
}
__device__ __forceinline__ unsigned pkh2(float a, float b) {
    __half2 h = __floats2half2_rn(a, b);
    return *(unsigned*)&h;
}

// two-level grid barrier (round-12, measured best)
__device__ __forceinline__ void gridbar(int nb) {
    __threadfence();
    __syncthreads();
    if (threadIdx.x == 0) {
        unsigned gen = g_gen;
        int grp = blockIdx.x & 7;
        unsigned quota = (unsigned)((nb - grp + 7) >> 3);
        unsigned v = atomicAdd(&g_cnt2[grp * 16], 1);
        if (v == quota - 1) {
            g_cnt2[grp * 16] = 0;
            unsigned r = atomicAdd(&g_root, 1);
            if (r == 7) {
                g_root = 0;
                __threadfence();
                g_gen = gen + 1;
            } else {
                while (g_gen == gen) __nanosleep(32);
            }
        } else {
            while (g_gen == gen) __nanosleep(32);
        }
    }
    __syncthreads();
}

// ---------------- K0: merged setup (state init + conv A + conv B) ----------------
__global__ void k_setup(const float* __restrict__ mem, const float* __restrict__ stop,
                        const float* __restrict__ ih, const float* __restrict__ ic,
                        const float* __restrict__ ii,
                        const float* __restrict__ attn_wm, const float* __restrict__ hop_wm) {
    int gtid = blockIdx.x * blockDim.x + threadIdx.x;
    if (gtid < MPTS) g_sel[gtid] = 0;
    if (gtid < HID) { g_hbuf[0][gtid] = ih[gtid]; g_cbuf[0][gtid] = ic[gtid];
                      g_x[gtid] = ii[gtid]; g_qh[gtid] = 0.f; }
    if (gtid < 128) g_cnt2[gtid] = 0;
    if (gtid == 0) { g_done = 0; g_ticket = 0; g_gen = 0; g_root = 0; g_xready = 0; }
    if (gtid < 2 * 512 * 512) {
        int w = gtid >> 18;
        int r = gtid & 262143;
        int n = r >> 9;
        int k = r & 511;
        const float* src = w ? hop_wm : attn_wm;
        g_bt[w][n][k] = __float2half_rn(src[(size_t)k * 512 + n]);
    }
    const int total4 = PADM * DIM / 4;
    for (int i = gtid; i < total4; i += gridDim.x * blockDim.x) {
        int row = i >> 7;
        int c4 = (i & 127) * 4;
        float4 v;
        if (row < NPTS)       v = *(const float4*)&mem[(size_t)row * DIM + c4];
        else if (row == NPTS) v = *(const float4*)&stop[c4];
        else                  v = make_float4(0.f, 0.f, 0.f, 0.f);
        uint2 ph;
        ph.x = pkh2(v.x, v.y); ph.y = pkh2(v.z, v.w);
        ((uint2*)g_a16)[i] = ph;
    }
}

// ---------------- GEMM: fp16 mma.sync, CTA 128x128, K=512, chunk 64 ----------------
__global__ void __launch_bounds__(256, 2) k_feat_mma() {
    extern __shared__ __align__(16) __half dsm[];
    int tid = threadIdx.x, wid = tid >> 5, lane = tid & 31;
    int rowBase = blockIdx.y * 128;
    int colBase = (blockIdx.x >> 1) * 128;
    int mat = blockIdx.x & 1;
    const __half* bsrc = &g_bt[mat][colBase][0];
    __half* outp = mat ? g_hf16 : g_af16;
    const __half* asrc = g_a16 + (size_t)rowBase * DIM;
    int wm = wid >> 1, wn = wid & 1;

    float acc[2][8][4];
#pragma unroll
    for (int mt = 0; mt < 2; mt++)
#pragma unroll
        for (int j = 0; j < 8; j++)
#pragma unroll
            for (int e = 0; e < 4; e++) acc[mt][j][e] = 0.f;

    uint32_t u0 = s2u(dsm);

    auto load = [&](int c, int buf) {
        const __half* A = asrc + c * 64;
        const __half* B = bsrc + c * 64;
        uint32_t dA = u0 + buf * (STGH * 2);
        uint32_t dB = dA + 128 * 72 * 2;
#pragma unroll
        for (int i = 0; i < 4; i++) {
            int idx = i * 256 + tid;
            int r = idx >> 3, ch = idx & 7;
            cp16(dA + r * 144 + ch * 16, (const char*)(A + (size_t)r * 512) + ch * 16);
            cp16(dB + r * 144 + ch * 16, (const char*)(B + (size_t)r * 512) + ch * 16);
        }
        asm volatile("cp.async.commit_group;" ::: "memory");
    };

    load(0, 0);
    for (int c = 0; c < NCH; c++) {
        int buf = c & 1;
        if (c + 1 < NCH) load(c + 1, buf ^ 1);
        if (c + 1 < NCH)
            asm volatile("cp.async.wait_group 1;" ::: "memory");
        else
            asm volatile("cp.async.wait_group 0;" ::: "memory");
        __syncthreads();

        uint32_t bA = u0 + buf * (STGH * 2);
        uint32_t bB = bA + 128 * 72 * 2;
#pragma unroll
        for (int ks = 0; ks < 4; ks++) {
            uint32_t a[2][4];
#pragma unroll
            for (int mt = 0; mt < 2; mt++) {
                int row = wm * 32 + mt * 16 + (lane & 15);
                int col = ks * 16 + (lane >> 4) * 8;
                ldm4(a[mt][0], a[mt][1], a[mt][2], a[mt][3], bA + (row * 72 + col) * 2);
            }
            uint32_t b[4][4];
#pragma unroll
            for (int p = 0; p < 4; p++) {
                int q = lane >> 3, rr = lane & 7;
                int n = wn * 64 + p * 16 + (q >> 1) * 8 + rr;
                int col = ks * 16 + (q & 1) * 8;
                ldm4(b[p][0], b[p][1], b[p][2], b[p][3], bB + (n * 72 + col) * 2);
            }
#pragma unroll
            for (int mt = 0; mt < 2; mt++)
#pragma unroll
                for (int j = 0; j < 8; j++)
                    mma16816(acc[mt][j], a[mt][0], a[mt][1], a[mt][2], a[mt][3],
                             b[j >> 1][(j & 1) * 2], b[j >> 1][(j & 1) * 2 + 1]);
        }
        __syncthreads();
    }

    int g = lane >> 2, tq = lane & 3;
#pragma unroll
    for (int mt = 0; mt < 2; mt++) {
        int r0 = rowBase + wm * 32 + mt * 16 + g;
#pragma unroll
        for (int j = 0; j < 8; j++) {
            int cc = colBase + wn * 64 + j * 8 + tq * 2;
            if (r0 < MPTS)
                *(__half2*)&outp[(size_t)r0 * DIM + cc] =
                    __floats2half2_rn(acc[mt][j][0], acc[mt][j][1]);
            if (r0 + 8 < MPTS)
                *(__half2*)&outp[(size_t)(r0 + 8) * DIM + cc] =
                    __floats2half2_rn(acc[mt][j][2], acc[mt][j][3]);
        }
    }
}

// ================= persistent step megakernel (round-12 layout: strided rows) =================
__global__ void __launch_bounds__(256, 2) k_step(
    const float* __restrict__ w_ih, const float* __restrict__ w_hh,
    const float* __restrict__ b_ih, const float* __restrict__ b_hh,
    const float* __restrict__ hop_wq, const float* __restrict__ hop_v,
    const float* __restrict__ attn_wq, const float* __restrict__ attn_v,
    const float* __restrict__ gumbel, const float* __restrict__ attn_mem,
    const float* __restrict__ stop, float* __restrict__ out, int nb)
{
    __shared__ float sg2[8][4];
    __shared__ float shh[4];
    __shared__ float smx[8], ssw[8], sacc[8][512];
    __shared__ float red[256];
    __shared__ float qn[8];
    __shared__ float sb[8]; __shared__ int si[8];
    __shared__ float sm[8]; __shared__ float ss[8];
    __shared__ float fb[256]; __shared__ int fi[256];
    __shared__ float fm[256]; __shared__ float fs[256];
    __shared__ int s_out, s_nd, islast;

    int bid = blockIdx.x;
    int tid = threadIdx.x, wid = tid >> 5, lane = tid & 31;
    const int tot = nb * 8;

    for (int t = 0; t < TSTEPS; t++) {
        // ---- phase A (flag-gated): gates + h,c + qh GEMV (blocks 0..127) ----
        if (bid < 128) {
            if (tid == 0) { while (g_xready < t) __nanosleep(32); }
            __syncthreads();
            __threadfence();
            int kb = bid * 4;
            const float* hold = g_hbuf[t & 1];
            float* hnew = g_hbuf[(t + 1) & 1];
            const float* cold = g_cbuf[t & 1];
            float* cnew = g_cbuf[(t + 1) & 1];
            int j = kb + (wid & 3);
            int k0 = (wid >> 2) * 256;
            const float* wi0 = w_ih + (size_t)j * DIM;
            const float* wi1 = w_ih + (size_t)(HID + j) * DIM;
            const float* wi2 = w_ih + (size_t)(2 * HID + j) * DIM;
            const float* wi3 = w_ih + (size_t)(3 * HID + j) * DIM;
            const float* wh0 = w_hh + (size_t)j * HID;
            const float* wh1 = w_hh + (size_t)(HID + j) * HID;
            const float* wh2 = w_hh + (size_t)(2 * HID + j) * HID;
            const float* wh3 = w_hh + (size_t)(3 * HID + j) * HID;
            float s0 = 0.f, s1 = 0.f, s2 = 0.f, s3 = 0.f;
#pragma unroll 4
            for (int k = k0 + lane; k < k0 + 256; k += 32) {
                float xv = g_x[k], hv = hold[k];
                s0 += wi0[k] * xv + wh0[k] * hv;
                s1 += wi1[k] * xv + wh1[k] * hv;
                s2 += wi2[k] * xv + wh2[k] * hv;
                s3 += wi3[k] * xv + wh3[k] * hv;
            }
#pragma unroll
            for (int o = 16; o; o >>= 1) {
                s0 += __shfl_xor_sync(0xffffffffu, s0, o);
                s1 += __shfl_xor_sync(0xffffffffu, s1, o);
                s2 += __shfl_xor_sync(0xffffffffu, s2, o);
                s3 += __shfl_xor_sync(0xffffffffu, s3, o);
            }
            if (!lane) { sg2[wid][0] = s0; sg2[wid][1] = s1; sg2[wid][2] = s2; sg2[wid][3] = s3; }
            __syncthreads();
            if (tid < 4) {
                int jj = kb + tid;
                float g0 = sg2[tid][0] + sg2[tid + 4][0] + b_ih[jj] + b_hh[jj];
                float g1 = sg2[tid][1] + sg2[tid + 4][1] + b_ih[HID + jj] + b_hh[HID + jj];
                float g2 = sg2[tid][2] + sg2[tid + 4][2] + b_ih[2 * HID + jj] + b_hh[2 * HID + jj];
                float g3 = sg2[tid][3] + sg2[tid + 4][3] + b_ih[3 * HID + jj] + b_hh[3 * HID + jj];
                float gi = sigm(g0);
                float gf = sigm(g1);
                float gg = tanhe(g2);
                float go = sigm(g3);
                float c = gf * cold[jj] + gi * gg;
                float h = go * tanhe(c);
                cnew[jj] = c;
                hnew[jj] = h;
                shh[tid] = h;
            }
            __syncthreads();
            float a0 = 0.f, a1 = 0.f;
#pragma unroll
            for (int kk = 0; kk < 4; kk++) {
                float hv = shh[kk];
                const float* wr = hop_wq + (size_t)(kb + kk) * HID;
                a0 += hv * wr[tid];
                a1 += hv * wr[tid + 256];
            }
            atomicAdd(&g_qh[tid], a0);
            atomicAdd(&g_qh[tid + 256], a1);
        }
        gridbar(nb);

        // ---- phase B: hop pass (strided rows, 4/iter) ----
        {
            if (bid == 0) { g_ba[tid] = 0.f; g_ba[tid + 256] = 0.f; }
            int gw = bid * 8 + wid;
            float q0[16], v0[16];
            {
                float4 a = *(const float4*)&g_qh[lane * 8];
                float4 b = *(const float4*)&g_qh[lane * 8 + 4];
                float4 c = *(const float4*)&g_qh[256 + lane * 8];
                float4 d = *(const float4*)&g_qh[256 + lane * 8 + 4];
                q0[0]=a.x;q0[1]=a.y;q0[2]=a.z;q0[3]=a.w; q0[4]=b.x;q0[5]=b.y;q0[6]=b.z;q0[7]=b.w;
                q0[8]=c.x;q0[9]=c.y;q0[10]=c.z;q0[11]=c.w; q0[12]=d.x;q0[13]=d.y;q0[14]=d.z;q0[15]=d.w;
                a = *(const float4*)&hop_v[lane * 8];
                b = *(const float4*)&hop_v[lane * 8 + 4];
                c = *(const float4*)&hop_v[256 + lane * 8];
                d = *(const float4*)&hop_v[256 + lane * 8 + 4];
                v0[0]=a.x;v0[1]=a.y;v0[2]=a.z;v0[3]=a.w; v0[4]=b.x;v0[5]=b.y;v0[6]=b.z;v0[7]=b.w;
                v0[8]=c.x;v0[9]=c.y;v0[10]=c.z;v0[11]=c.w; v0[12]=d.x;v0[13]=d.y;v0[14]=d.z;v0[15]=d.w;
            }
            float mx = NEGINF, sw = 0.f, acc[16];
#pragma unroll
            for (int i = 0; i < 16; i++) acc[i] = 0.f;

            for (int m0 = gw * 4; m0 < MPTS; m0 += 4 * tot) {
                uint4 p[4][2];
                int nrow = MPTS - m0;
                if (nrow > 4) nrow = 4;
#pragma unroll
                for (int r = 0; r < 4; r++) {
                    if (r < nrow) {
                        const uint4* rp = (const uint4*)(g_hf16 + (size_t)(m0 + r) * DIM);
                        p[r][0] = rp[lane];
                        p[r][1] = rp[32 + lane];
                    }
                }
                float sp[4];
#pragma unroll
                for (int r = 0; r < 4; r++) {
                    sp[r] = 0.f;
                    if (r < nrow) {
#pragma unroll
                        for (int k = 0; k < 4; k++) {
                            float2 f0 = __half22float2(((const __half2*)&p[r][0])[k]);
                            float2 f1 = __half22float2(((const __half2*)&p[r][1])[k]);
                            sp[r] += tanha(f0.x + q0[2*k])     * v0[2*k];
                            sp[r] += tanha(f0.y + q0[2*k+1])   * v0[2*k+1];
                            sp[r] += tanha(f1.x + q0[8+2*k])   * v0[8+2*k];
                            sp[r] += tanha(f1.y + q0[8+2*k+1]) * v0[8+2*k+1];
                        }
                    }
                }
#pragma unroll
                for (int o = 16; o; o >>= 1) {
                    sp[0] += __shfl_xor_sync(0xffffffffu, sp[0], o);
                    sp[1] += __shfl_xor_sync(0xffffffffu, sp[1], o);
                    sp[2] += __shfl_xor_sync(0xffffffffu, sp[2], o);
                    sp[3] += __shfl_xor_sync(0xffffffffu, sp[3], o);
                }
#pragma unroll
                for (int r = 0; r < 4; r++) {
                    if (r >= nrow) break;
                    if (sp[r] > mx) {
                        float f = __expf(mx - sp[r]);
                        sw *= f;
#pragma unroll
                        for (int i = 0; i < 16; i++) acc[i] *= f;
                        mx = sp[r];
                    }
                    float wgt = __expf(sp[r] - mx);
                    sw += wgt;
#pragma unroll
                    for (int k = 0; k < 4; k++) {
                        float2 f0 = __half22float2(((const __half2*)&p[r][0])[k]);
                        float2 f1 = __half22float2(((const __half2*)&p[r][1])[k]);
                        acc[2*k]     += wgt * f0.x;
                        acc[2*k+1]   += wgt * f0.y;
                        acc[8+2*k]   += wgt * f1.x;
                        acc[8+2*k+1] += wgt * f1.y;
                    }
                }
            }
#pragma unroll
            for (int s = 0; s < 8; s++) {
                sacc[wid][lane * 8 + s] = acc[s];
                sacc[wid][256 + lane * 8 + s] = acc[8 + s];
            }
            if (!lane) { smx[wid] = mx; ssw[wid] = sw; }
            __syncthreads();

            float M = smx[0];
#pragma unroll
            for (int w = 1; w < 8; w++) M = fmaxf(M, smx[w]);
            for (int c = tid; c < 512; c += 256) {
                float a = 0.f;
#pragma unroll
                for (int w = 0; w < 8; w++) a += sacc[w][c] * __expf(smx[w] - M);
                g_hpart[bid][2 + c] = a;
            }
            if (tid == 0) {
                float W = 0.f;
#pragma unroll
                for (int w = 0; w < 8; w++) W += ssw[w] * __expf(smx[w] - M);
                g_hpart[bid][0] = M;
                g_hpart[bid][1] = W;
            }
            __syncthreads();
        }
        gridbar(nb);

        // ---- phase C: reduce hop partials + bias GEMV (blocks 0..63) ----
        if (bid < 64) {
            int kb = bid * 8;
            float m = NEGINF;
            for (int b = tid; b < nb; b += 256) m = fmaxf(m, g_hpart[b][0]);
            red[tid] = m; __syncthreads();
            for (int o = 128; o; o >>= 1) { if (tid < o) red[tid] = fmaxf(red[tid], red[tid + o]); __syncthreads(); }
            float M = red[0]; __syncthreads();

            float wsum = 0.f;
            for (int b = tid; b < nb; b += 256) wsum += __expf(g_hpart[b][0] - M) * g_hpart[b][1];
            red[tid] = wsum; __syncthreads();
            for (int o = 128; o; o >>= 1) { if (tid < o) red[tid] += red[tid + o]; __syncthreads(); }
            float W = red[0]; __syncthreads();

            {
                int g = tid >> 5, l = tid & 31;
                int k = kb + g;
                float a = 0.f;
                for (int b = l; b < nb; b += 32)
                    a += __expf(g_hpart[b][0] - M) * g_hpart[b][2 + k];
#pragma unroll
                for (int o = 16; o; o >>= 1) a += __shfl_xor_sync(0xffffffffu, a, o);
                if (l == 0) qn[g] = __fdividef(a, W);
            }
            __syncthreads();

            float a0 = 0.f, a1 = 0.f;
#pragma unroll
            for (int kk = 0; kk < 8; kk++) {
                float q = qn[kk];
                const float* wr = attn_wq + (size_t)(kb + kk) * HID;
                a0 += q * wr[tid];
                a1 += q * wr[tid + 256];
            }
            atomicAdd(&g_ba[tid], a0);
            atomicAdd(&g_ba[tid + 256], a1);
        }
        gridbar(nb);

        // ---- phase D: attn pass (strided rows) + ticket-fused final + flag ----
        {
            int gw = bid * 8 + wid;
            const float* gum = gumbel + (size_t)t * MPTS;
            float b0[16], v0[16];
            {
                float4 a = *(const float4*)&g_ba[lane * 8];
                float4 b = *(const float4*)&g_ba[lane * 8 + 4];
                float4 c = *(const float4*)&g_ba[256 + lane * 8];
                float4 d = *(const float4*)&g_ba[256 + lane * 8 + 4];
                b0[0]=a.x;b0[1]=a.y;b0[2]=a.z;b0[3]=a.w; b0[4]=b.x;b0[5]=b.y;b0[6]=b.z;b0[7]=b.w;
                b0[8]=c.x;b0[9]=c.y;b0[10]=c.z;b0[11]=c.w; b0[12]=d.x;b0[13]=d.y;b0[14]=d.z;b0[15]=d.w;
                a = *(const float4*)&attn_v[lane * 8];
                b = *(const float4*)&attn_v[lane * 8 + 4];
                c = *(const float4*)&attn_v[256 + lane * 8];
                d = *(const float4*)&attn_v[256 + lane * 8 + 4];
                v0[0]=a.x;v0[1]=a.y;v0[2]=a.z;v0[3]=a.w; v0[4]=b.x;v0[5]=b.y;v0[6]=b.z;v0[7]=b.w;
                v0[8]=c.x;v0[9]=c.y;v0[10]=c.z;v0[11]=c.w; v0[12]=d.x;v0[13]=d.y;v0[14]=d.z;v0[15]=d.w;
            }
            float mxs = NEGINF, ssum = 0.f, best = NEGINF;
            int bidx = 0x7fffffff;

            for (int m0 = gw * 4; m0 < MPTS; m0 += 4 * tot) {
                uint4 p[4][2];
                int nrow = MPTS - m0;
                if (nrow > 4) nrow = 4;
#pragma unroll
                for (int r = 0; r < 4; r++) {
                    if (r < nrow) {
                        const uint4* rp = (const uint4*)(g_af16 + (size_t)(m0 + r) * DIM);
                        p[r][0] = rp[lane];
                        p[r][1] = rp[32 + lane];
                    }
                }
#pragma unroll
                for (int r = 0; r < 4; r++) {
                    if (r >= nrow) break;
                    int m = m0 + r;
                    float sp = 0.f;
#pragma unroll
                    for (int k = 0; k < 4; k++) {
                        float2 f0 = __half22float2(((const __half2*)&p[r][0])[k]);
                        float2 f1 = __half22float2(((const __half2*)&p[r][1])[k]);
                        sp += tanha(f0.x + b0[2*k])     * v0[2*k];
                        sp += tanha(f0.y + b0[2*k+1])   * v0[2*k+1];
                        sp += tanha(f1.x + b0[8+2*k])   * v0[8+2*k];
                        sp += tanha(f1.y + b0[8+2*k+1]) * v0[8+2*k+1];
                    }
#pragma unroll
                    for (int o = 16; o; o >>= 1) sp += __shfl_xor_sync(0xffffffffu, sp, o);
                    float sc = g_sel[m] ? -1e18f : sp;
                    if (sc > mxs) { ssum *= __expf(mxs - sc); mxs = sc; }
                    ssum += __expf(sc - mxs);
                    float tv = sc + gum[m];
                    if (tv > best || (tv == best && m < bidx)) { best = tv; bidx = m; }
                }
            }
            if (!lane) { sb[wid] = best; si[wid] = bidx; sm[wid] = mxs; ss[wid] = ssum; }
            __syncthreads();
            if (tid == 0) {
                float B = sb[0]; int I = si[0];
                float M2 = sm[0], S = ss[0];
#pragma unroll
                for (int w = 1; w < 8; w++) {
                    if (sb[w] > B || (sb[w] == B && si[w] < I)) { B = sb[w]; I = si[w]; }
                    float m2 = sm[w], s2 = ss[w];
                    if (m2 > M2) { S = S * __expf(M2 - m2) + s2; M2 = m2; }
                    else S += s2 * __expf(m2 - M2);
                }
                g_apart[bid][0] = B; g_apart[bid][1] = M2;
                g_apart[bid][2] = S; g_aidx[bid] = I;
            }

            __threadfence();
            __syncthreads();
            if (tid == 0) {
                int v = atomicAdd(&g_ticket, 1);
                islast = ((v % nb) == nb - 1);
            }
            __syncthreads();
            if (islast) {
                g_qh[tid] = 0.f; g_qh[tid + 256] = 0.f;
                float B = NEGINF; int I = 0x7fffffff; float M = NEGINF; float S = 0.f;
                for (int b = tid; b < nb; b += 256) {
                    float bb = g_apart[b][0]; int ii = g_aidx[b];
                    if (bb > B || (bb == B && ii < I)) { B = bb; I = ii; }
                    float m2 = g_apart[b][1], s2 = g_apart[b][2];
                    if (m2 > M) { S = S * __expf(M - m2) + s2; M = m2; }
                    else S += s2 * __expf(m2 - M);
                }
                fb[tid] = B; fi[tid] = I; fm[tid] = M; fs[tid] = S;
                __syncthreads();
                for (int o = 128; o; o >>= 1) {
                    if (tid < o) {
                        if (fb[tid + o] > fb[tid] || (fb[tid + o] == fb[tid] && fi[tid + o] < fi[tid])) {
                            fb[tid] = fb[tid + o]; fi[tid] = fi[tid + o];
                        }
                        float m1 = fm[tid], s1 = fs[tid];
                        float m2 = fm[tid + o], s2 = fs[tid + o];
                        float Mn = fmaxf(m1, m2);
                        float Sn = 0.f;
                        if (s1 > 0.f) Sn += s1 * __expf(m1 - Mn);
                        if (s2 > 0.f) Sn += s2 * __expf(m2 - Mn);
                        fm[tid] = Mn; fs[tid] = Sn;
                    }
                    __syncthreads();
                }
                if (tid == 0) {
                    int done = g_done;
                    int o_ = fi[0];
                    float sc = fb[0] - gum[o_];
                    float lse = fm[0] + logf(fs[0]);
                    float logp = sc - lse;
                    out[t]          = done ? (float)NPTS : (float)o_;
                    out[TSTEPS + t] = done ? 0.f : logp;
                    if (!done) g_sel[o_] = 1;
                    int nd = done || (o_ == NPTS);
                    g_done = nd;
                    s_out = o_; s_nd = nd;
                }
                __syncthreads();
                if (!s_nd) {
                    int o_ = s_out;
                    const float* src = (o_ == NPTS) ? stop : attn_mem + (size_t)o_ * DIM;
                    g_x[tid] = src[tid];
                    g_x[tid + 256] = src[tid + 256];
                }
                __threadfence();
                __syncthreads();
                if (tid == 0) g_xready = t + 1;
            }
        }
        // phase A of t+1 is flag-gated; no trailing gridbar
    }
}

// ---------------- launch ----------------
extern "C" void kernel_launch(void* const* d_in, const int* in_sizes, int n_in,
                              void* d_out, int out_size) {
    const float* attn_mem = (const float*)d_in[0];
    const float* stop     = (const float*)d_in[1];
    const float* init_h   = (const float*)d_in[2];
    const float* init_c   = (const float*)d_in[3];
    const float* init_i   = (const float*)d_in[4];
    const float* attn_wm  = (const float*)d_in[5];
    const float* attn_wq  = (const float*)d_in[6];
    const float* attn_v   = (const float*)d_in[7];
    const float* hop_wm   = (const float*)d_in[8];
    const float* hop_wq   = (const float*)d_in[9];
    const float* hop_v    = (const float*)d_in[10];
    const float* w_ih     = (const float*)d_in[11];
    const float* w_hh     = (const float*)d_in[12];
    const float* b_ih     = (const float*)d_in[13];
    const float* b_hh     = (const float*)d_in[14];
    const float* gumbel   = (const float*)d_in[15];
    float* out = (float*)d_out;

    static int nb = 0;
    if (nb == 0) {
        int sms = 0;
        cudaDeviceGetAttribute(&sms, cudaDevAttrMultiProcessorCount, 0);
        nb = 2 * sms;
        if (nb > NBMAX) nb = NBMAX;
        if (nb < 128) nb = 128;
        cudaFuncSetAttribute(k_feat_mma, cudaFuncAttributeMaxDynamicSharedMemorySize, FEAT_SMEM);
    }

    k_setup<<<8192, 256>>>(attn_mem, stop, init_h, init_c, init_i, attn_wm, hop_wm);

    dim3 gg(8, ROWT);
    k_feat_mma<<<gg, 256, FEAT_SMEM>>>();

    k_step<<<nb, 256>>>(w_ih, w_hh, b_ih, b_hh, hop_wq, hop_v,
                        attn_wq, attn_v, gumbel, attn_mem, stop, out, nb);
}